// round 3
// baseline (speedup 1.0000x reference)
#include <cuda_runtime.h>

typedef unsigned long long ull;

__device__ __forceinline__ ull pack2(float lo, float hi){
    ull r; asm("mov.b64 %0, {%1, %2};" : "=l"(r) : "f"(lo), "f"(hi)); return r;
}
__device__ __forceinline__ void unpack2(ull v, float& lo, float& hi){
    asm("mov.b64 {%0, %1}, %2;" : "=f"(lo), "=f"(hi) : "l"(v));
}
__device__ __forceinline__ void fma2(ull& acc, ull a, ull b){
    asm("fma.rn.f32x2 %0, %1, %2, %0;" : "+l"(acc) : "l"(a), "l"(b));
}
__device__ __forceinline__ float leaky(float v){ return v > 0.f ? v : 0.01f*v; }

// ---------------- scratch (device globals; no runtime allocation) ----------------
__device__ float g_h[(size_t)2*64*94*94*94];   // c1 output (after leaky), 425 MB
__device__ float g_wc1[2*32*27*64];            // modulated c1 weights  [n][i][k][o]
__device__ float g_wc2[2*64*27*64];            // modulated c2 weights  [n][i][k][o]
__device__ float g_wskip[2*32*64];             // modulated skip weights [n][i][o]

// ---------------- prep: style MLP + weight modulation/demodulation ----------------
__global__ void prep_kernel(const float* __restrict__ s,
                            const float* __restrict__ w1, const float* __restrict__ b1,
                            const float* __restrict__ w2, const float* __restrict__ b2,
                            const float* __restrict__ w3, const float* __restrict__ b3,
                            const float* __restrict__ wc,
                            float* __restrict__ gw,
                            int H1, int H2, int ICn, int Kn)
{
    const int n   = blockIdx.x;
    const int tid = threadIdx.x;
    __shared__ float sv[64], a1[128], a2[128], mod[64], dem[64];
    if (tid < 64) sv[tid] = s[n*64 + tid];
    __syncthreads();
    if (tid < H1){
        float acc = b1[tid];
        for (int k = 0; k < 64; k++) acc += sv[k]*w1[tid*64 + k];
        a1[tid] = leaky(acc);
    }
    __syncthreads();
    if (tid < H2){
        float acc = b2[tid];
        for (int k = 0; k < H1; k++) acc += a1[k]*w2[tid*H1 + k];
        a2[tid] = leaky(acc);
    }
    __syncthreads();
    if (tid < ICn){
        float acc = b3[tid];
        for (int k = 0; k < H2; k++) acc += a2[k]*w3[tid*H2 + k];
        mod[tid] = acc;
    }
    __syncthreads();
    if (tid < 64){                 // per output channel: demod scalar
        float ssum = 0.f;
        for (int i = 0; i < ICn; i++){
            float m = mod[i];
            const float* wp = wc + (tid*ICn + i)*Kn;
            for (int k = 0; k < Kn; k++){ float t = wp[k]*m; ssum += t*t; }
        }
        dem[tid] = rsqrtf(ssum + 1e-8f);
    }
    __syncthreads();
    const int total = ICn*Kn*64;
    for (int e = tid; e < total; e += blockDim.x){
        int o = e & 63;
        int r = e >> 6;
        int k = r % Kn;
        int i = r / Kn;
        gw[n*total + e] = wc[(o*ICn + i)*Kn + k] * mod[i] * dem[o];
    }
}

// ---------------- output store helper ----------------
template<int OUTD>
__device__ __forceinline__ void store_row(float* __restrict__ out, int n, int oc,
                                          int oz, int oy, int gx0, const float* v)
{
    int base = ((n*64 + oc)*OUTD + oz)*OUTD*OUTD + oy*OUTD + gx0;
    if constexpr ((OUTD & 3) == 0){
        #pragma unroll
        for (int g = 0; g < 2; g++){
            if (gx0 + 4*g + 3 < OUTD)
                *(float4*)(out + base + 4*g) = make_float4(v[4*g], v[4*g+1], v[4*g+2], v[4*g+3]);
        }
    } else {
        #pragma unroll
        for (int g = 0; g < 4; g++){
            int xs = gx0 + 2*g;
            if (xs + 1 < OUTD)
                *(float2*)(out + base + 2*g) = make_float2(v[2*g], v[2*g+1]);
            else if (xs < OUTD)
                out[base + 2*g] = v[2*g];
        }
    }
}

// ---------------- direct 3x3x3 conv, packed f32x2 micro-kernel ----------------
// CTA: 64 oc x (4z x 4y x 16x) voxels, 256 threads.
// Thread: 8 oc (4 f32x2 pairs) x 8 consecutive-x voxels = 32 ull accumulators.
// Smem per ic-chunk(8): input halo tile [8][6][6][20] + weights [8][27][64].
template<int IC, int IND, int OUTD, bool FUSE_SKIP>
__global__ __launch_bounds__(256, 2)
void conv3d_kernel(const float* __restrict__ in,     // [2][IC][IND^3]
                   const float* __restrict__ wbuf,   // [2][IC][27][64]
                   const float* __restrict__ bias1,  // [64]
                   const float* __restrict__ xsrc,   // x, for fused skip
                   const float* __restrict__ wskip,  // [2][32][64]
                   const float* __restrict__ bias2,  // skip bias
                   float* __restrict__ out)          // [2][64][OUTD^3]
{
    constexpr int BZ = (OUTD + 3) / 4;
    extern __shared__ float smem[];
    float* s_in = smem;           // 8*6*6*20 = 5760 floats
    float* s_w  = smem + 5760;    // 8*27*64 = 13824 floats

    const int tid = threadIdx.x;
    const int ocg = tid & 7;          // 0..7 -> oc base
    const int vg  = tid >> 3;         // 0..31
    const int tz  = vg >> 3;          // 0..3
    const int ty  = (vg >> 1) & 3;    // 0..3
    const int xb  = (vg & 1) * 8;     // 0 or 8
    const int ob  = ocg * 8;

    const int bx = blockIdx.x, by = blockIdx.y;
    const int n  = blockIdx.z / BZ;
    const int bz = blockIdx.z % BZ;
    const int z0 = bz*4, y0 = by*4, x0c = bx*16;

    const float* inb = in + (size_t)n * IC * IND * IND * IND;

    ull acc[4][8];
    #pragma unroll
    for (int p = 0; p < 4; p++)
        #pragma unroll
        for (int v = 0; v < 8; v++) acc[p][v] = 0ull;

    #pragma unroll 1
    for (int ic0 = 0; ic0 < IC; ic0 += 8){
        __syncthreads();
        // cooperative load: input halo tile (zero-fill out of range)
        #pragma unroll 1
        for (int e = tid; e < 8*6*6*18; e += 256){
            int xx = e % 18; int t = e / 18;
            int yy = t % 6;  t /= 6;
            int zz = t % 6;  int ic = t / 6;
            int gz = z0 + zz, gy = y0 + yy, gx = x0c + xx;
            float v = 0.f;
            if (gz < IND && gy < IND && gx < IND)
                v = inb[((ic0 + ic)*IND + gz)*(IND*IND) + gy*IND + gx];
            s_in[((ic*6 + zz)*6 + yy)*20 + xx] = v;
        }
        // cooperative load: weight chunk (contiguous)
        {
            const float4* wsrc = (const float4*)(wbuf + ((size_t)n*IC + ic0)*27*64);
            float4* wdst = (float4*)s_w;
            #pragma unroll 1
            for (int e = tid; e < 8*27*16; e += 256) wdst[e] = wsrc[e];
        }
        __syncthreads();

        #pragma unroll 1
        for (int ic = 0; ic < 8; ic++){
            #pragma unroll
            for (int kz = 0; kz < 3; kz++){
                #pragma unroll
                for (int ky = 0; ky < 3; ky++){
                    const float* r = s_in + ((ic*6 + tz + kz)*6 + (ty + ky))*20 + xb;
                    float4 ra = *(const float4*)r;
                    float4 rb = *(const float4*)(r + 4);
                    float2 rc = *(const float2*)(r + 8);
                    ull dup[10];
                    dup[0] = pack2(ra.x, ra.x); dup[1] = pack2(ra.y, ra.y);
                    dup[2] = pack2(ra.z, ra.z); dup[3] = pack2(ra.w, ra.w);
                    dup[4] = pack2(rb.x, rb.x); dup[5] = pack2(rb.y, rb.y);
                    dup[6] = pack2(rb.z, rb.z); dup[7] = pack2(rb.w, rb.w);
                    dup[8] = pack2(rc.x, rc.x); dup[9] = pack2(rc.y, rc.y);
                    const float* wrow = s_w + ((ic*9 + kz*3 + ky)*3)*64 + ob;
                    #pragma unroll
                    for (int kx = 0; kx < 3; kx++){
                        const ull* wp = (const ull*)(wrow + kx*64);   // pairs (2o,2o+1), 8B aligned
                        ull w0 = wp[0], w1 = wp[1], w2 = wp[2], w3 = wp[3];
                        #pragma unroll
                        for (int v = 0; v < 8; v++){
                            ull d = dup[v + kx];
                            fma2(acc[0][v], w0, d);
                            fma2(acc[1][v], w1, d);
                            fma2(acc[2][v], w2, d);
                            fma2(acc[3][v], w3, d);
                        }
                    }
                }
            }
        }
    }

    if constexpr (FUSE_SKIP){
        // fused 1x1 skip conv on x at cropped coords (+2 offset)
        float* s_xs = smem;          // [32][4][4][16] = 8192 floats
        float* s_ws = smem + 8192;   // [32][64]       = 2048 floats
        __syncthreads();
        const float* xbatch = xsrc + (size_t)n * 32 * 96 * 96 * 96;
        #pragma unroll 1
        for (int e = tid; e < 8192; e += 256){
            int xx = e & 15, yy = (e >> 4) & 3, zz = (e >> 6) & 3, ic = e >> 8;
            int gz = z0 + 2 + zz, gy = y0 + 2 + yy, gx = x0c + 2 + xx;
            float v = 0.f;
            if (gz < 96 && gy < 96 && gx < 96)
                v = xbatch[(ic*96 + gz)*9216 + gy*96 + gx];
            s_xs[e] = v;
        }
        #pragma unroll 1
        for (int e = tid; e < 2048; e += 256)
            s_ws[e] = wskip[n*2048 + e];
        __syncthreads();

        #pragma unroll 1
        for (int ic = 0; ic < 32; ic++){
            const ull* wp = (const ull*)(s_ws + ic*64 + ob);
            ull w0 = wp[0], w1 = wp[1], w2 = wp[2], w3 = wp[3];
            const float* xr = s_xs + ic*256 + (tz*4 + ty)*16 + xb;
            float4 xa = *(const float4*)xr;
            float4 xv = *(const float4*)(xr + 4);
            float xin[8] = {xa.x, xa.y, xa.z, xa.w, xv.x, xv.y, xv.z, xv.w};
            #pragma unroll
            for (int v = 0; v < 8; v++){
                ull d = pack2(xin[v], xin[v]);
                fma2(acc[0][v], w0, d);
                fma2(acc[1][v], w1, d);
                fma2(acc[2][v], w2, d);
                fma2(acc[3][v], w3, d);
            }
        }
    }

    // epilogue: bias (+skip bias), leaky, vectorized store
    const int oz = z0 + tz, oy = y0 + ty;
    if (oz < OUTD && oy < OUTD){
        const int gx0 = x0c + xb;
        #pragma unroll
        for (int p = 0; p < 4; p++){
            const int oc0 = ob + 2*p;
            float b0 = bias1[oc0],     b1v = bias1[oc0 + 1];
            if constexpr (FUSE_SKIP){ b0 += bias2[oc0]; b1v += bias2[oc0 + 1]; }
            float lo[8], hi[8];
            #pragma unroll
            for (int v = 0; v < 8; v++){
                float a, b;
                unpack2(acc[p][v], a, b);
                lo[v] = leaky(a + b0);
                hi[v] = leaky(b + b1v);
            }
            store_row<OUTD>(out, n, oc0,     oz, oy, gx0, lo);
            store_row<OUTD>(out, n, oc0 + 1, oz, oy, gx0, hi);
        }
    }
}

// ---------------- launch ----------------
static const int SMEM_BYTES = (5760 + 13824) * 4;   // 78336

extern "C" void kernel_launch(void* const* d_in, const int* in_sizes, int n_in,
                              void* d_out, int out_size)
{
    (void)in_sizes; (void)n_in; (void)out_size;

    const float* x        = (const float*)d_in[0];
    const float* s        = (const float*)d_in[1];
    const float* skip_w1  = (const float*)d_in[2];
    const float* skip_b1  = (const float*)d_in[3];
    const float* skip_w2  = (const float*)d_in[4];
    const float* skip_b2  = (const float*)d_in[5];
    const float* skip_w3  = (const float*)d_in[6];
    const float* skip_b3  = (const float*)d_in[7];
    const float* skip_wc  = (const float*)d_in[8];
    const float* skip_bc  = (const float*)d_in[9];
    const float* c1_w1    = (const float*)d_in[10];
    const float* c1_b1    = (const float*)d_in[11];
    const float* c1_w2    = (const float*)d_in[12];
    const float* c1_b2    = (const float*)d_in[13];
    const float* c1_w3    = (const float*)d_in[14];
    const float* c1_b3    = (const float*)d_in[15];
    const float* c1_wc    = (const float*)d_in[16];
    const float* c1_bc    = (const float*)d_in[17];
    const float* c2_w1    = (const float*)d_in[18];
    const float* c2_b1    = (const float*)d_in[19];
    const float* c2_w2    = (const float*)d_in[20];
    const float* c2_b2    = (const float*)d_in[21];
    const float* c2_w3    = (const float*)d_in[22];
    const float* c2_b3    = (const float*)d_in[23];
    const float* c2_wc    = (const float*)d_in[24];
    const float* c2_bc    = (const float*)d_in[25];

    float *p_h, *p_w1, *p_w2, *p_ws;
    cudaGetSymbolAddress((void**)&p_h,  g_h);
    cudaGetSymbolAddress((void**)&p_w1, g_wc1);
    cudaGetSymbolAddress((void**)&p_w2, g_wc2);
    cudaGetSymbolAddress((void**)&p_ws, g_wskip);

    cudaFuncSetAttribute((const void*)conv3d_kernel<32,96,94,false>,
                         cudaFuncAttributeMaxDynamicSharedMemorySize, SMEM_BYTES);
    cudaFuncSetAttribute((const void*)conv3d_kernel<64,94,92,true>,
                         cudaFuncAttributeMaxDynamicSharedMemorySize, SMEM_BYTES);

    // style MLPs + modulated/demodulated weights
    prep_kernel<<<2, 256>>>(s, skip_w1, skip_b1, skip_w2, skip_b2, skip_w3, skip_b3,
                            skip_wc, p_ws, 64, 64, 32, 1);
    prep_kernel<<<2, 256>>>(s, c1_w1, c1_b1, c1_w2, c1_b2, c1_w3, c1_b3,
                            c1_wc, p_w1, 64, 64, 32, 27);
    prep_kernel<<<2, 256>>>(s, c2_w1, c2_b1, c2_w2, c2_b2, c2_w3, c2_b3,
                            c2_wc, p_w2, 128, 128, 64, 27);

    // c1: x -> h (leaky applied)
    conv3d_kernel<32,96,94,false><<<dim3(6,24,48), 256, SMEM_BYTES>>>(
        x, p_w1, c1_bc, nullptr, nullptr, nullptr, p_h);

    // c2 + fused skip + biases + final leaky -> out
    conv3d_kernel<64,94,92,true><<<dim3(6,23,46), 256, SMEM_BYTES>>>(
        p_h, p_w2, c2_bc, x, p_ws, skip_bc, (float*)d_out);
}

// round 5
// speedup vs baseline: 1.8311x; 1.8311x over previous
#include <cuda_runtime.h>
#include <cstdint>

__device__ __forceinline__ float leaky(float v){ return v > 0.f ? v : 0.01f*v; }
__device__ __forceinline__ float tf32r(float v){
    uint32_t r; asm("cvt.rna.tf32.f32 %0, %1;" : "=r"(r) : "f"(v));
    return __uint_as_float(r);
}
__device__ __forceinline__ uint32_t smem_u32(const void* p){
    uint32_t a; asm("{ .reg .u64 t; cvta.to.shared.u64 t, %1; cvt.u32.u64 %0, t; }" : "=r"(a) : "l"(p));
    return a;
}
__device__ __forceinline__ void cpa16(uint32_t dst, const void* src, uint32_t sz){
    asm volatile("cp.async.cg.shared.global [%0], [%1], 16, %2;"
                 :: "r"(dst), "l"(src), "r"(sz) : "memory");
}
#define CP_COMMIT() asm volatile("cp.async.commit_group;" ::: "memory")
#define CP_WAIT1()  asm volatile("cp.async.wait_group 1;" ::: "memory")
#define CP_WAIT0()  asm volatile("cp.async.wait_group 0;" ::: "memory")

__device__ __forceinline__ void mma8(float* c, const uint32_t* a, uint32_t b0, uint32_t b1){
    asm volatile("mma.sync.aligned.m16n8k8.row.col.f32.tf32.tf32.f32 "
        "{%0,%1,%2,%3}, {%4,%5,%6,%7}, {%8,%9}, {%0,%1,%2,%3};"
        : "+f"(c[0]), "+f"(c[1]), "+f"(c[2]), "+f"(c[3])
        : "r"(a[0]), "r"(a[1]), "r"(a[2]), "r"(a[3]), "r"(b0), "r"(b1));
}

// ---------------- device scratch ----------------
__device__ float g_xcl[(size_t)2*96*96*96*32];   // x channels-last tf32
__device__ float g_h  [(size_t)2*94*94*94*64];   // h channels-last tf32
__device__ float g_wc1[2*27*2048];               // B fragments per 32-K chunk
__device__ float g_wc2[2*54*2048];
__device__ float g_wsk[2*2048];

// ---------------- prep: style MLP + modulate/demod + B-fragment tiles ----------------
__global__ void prep_kernel(const float* __restrict__ s,
                            const float* __restrict__ w1, const float* __restrict__ b1,
                            const float* __restrict__ w2, const float* __restrict__ b2,
                            const float* __restrict__ w3, const float* __restrict__ b3,
                            const float* __restrict__ wc, float* __restrict__ gw,
                            int H1, int H2, int IC, int KD)
{
    const int n = blockIdx.x, tid = threadIdx.x;
    __shared__ float sv[64], a1[128], a2[128], mod[64], dem[64];
    if (tid < 64) sv[tid] = s[n*64 + tid];
    __syncthreads();
    if (tid < H1){
        float a = b1[tid];
        for (int k = 0; k < 64; k++) a += sv[k]*w1[tid*64 + k];
        a1[tid] = leaky(a);
    }
    __syncthreads();
    if (tid < H2){
        float a = b2[tid];
        for (int k = 0; k < H1; k++) a += a1[k]*w2[tid*H1 + k];
        a2[tid] = leaky(a);
    }
    __syncthreads();
    if (tid < IC){
        float a = b3[tid];
        for (int k = 0; k < H2; k++) a += a2[k]*w3[tid*H2 + k];
        mod[tid] = a;
    }
    __syncthreads();
    if (tid < 64){
        float ss = 0.f;
        for (int i = 0; i < IC; i++){
            float m = mod[i];
            const float* wp = wc + (tid*IC + i)*KD;
            for (int k = 0; k < KD; k++){ float t = wp[k]*m; ss += t*t; }
        }
        dem[tid] = rsqrtf(ss + 1e-8f);
    }
    __syncthreads();
    // B fragment order per chunk: offset = ((s*8+nt)*32 + lane)*2 + r
    // b0 = W[oc=8nt+g][k=8s+t], b1 = W[oc][k=8s+t+4]
    const int nsub = IC >> 5;
    const int total = KD * nsub * 2048;
    for (int e = tid; e < total; e += blockDim.x){
        int c    = e >> 11;
        int pos  = e & 2047;
        int r    = pos & 1;
        int lane = (pos >> 1) & 31;
        int nt   = (pos >> 6) & 7;
        int ss_  = pos >> 9;
        int oc   = nt*8 + (lane >> 2);
        int kk   = ss_*8 + (lane & 3) + 4*r;
        int tap  = c / nsub, ih = c % nsub;
        int ic   = ih*32 + kk;
        gw[(size_t)n*total + e] = tf32r(wc[(oc*IC + ic)*KD + tap] * mod[ic] * dem[oc]);
    }
}

// ---------------- x -> channels-last tf32 ----------------
__global__ void xconvert_kernel(const float* __restrict__ x, float* __restrict__ xcl)
{
    const int y = blockIdx.x, z = blockIdx.y, n = blockIdx.z;
    __shared__ float sm[32*97];
    const float* src = x + (size_t)n*28311552 + (size_t)z*9216 + (size_t)y*96;
    for (int e = threadIdx.x; e < 32*96; e += 128){
        int ic = e / 96, xx = e % 96;
        sm[ic*97 + xx] = tf32r(src[(size_t)ic*884736 + xx]);
    }
    __syncthreads();
    float* dst = xcl + (size_t)n*28311552 + ((size_t)z*96 + y)*96*32;
    for (int e = threadIdx.x; e < 32*96; e += 128){
        int xx = e >> 5, ic = e & 31;
        dst[(size_t)xx*32 + ic] = sm[ic*97 + xx];
    }
}

// ---------------- implicit-GEMM conv via mma.sync tf32 ----------------
// CTA: 256 threads / 8 warps; tile M=256 voxels (4z x 4y x 16x) x N=64 oc.
// Warp strip = 32 M rows (2 x m16 frags). K chunks of 32 (tap x ic-half),
// double-buffered via cp.async.
// smem floats: A[2][256*36]=18432 | B[2][2048]=4096 | bias[64]  => 22592 fl = 90368 B
template<int IND, int OUTD, int INCH, int NCH, bool SKIP>
__global__ __launch_bounds__(256, 2)
void conv_mma(const float* __restrict__ in,     // channels-last tf32 [n][IND^3][INCH]
              const float* __restrict__ wtil,   // [n][NW][2048] B fragments
              const float* __restrict__ wskip,  // [n][2048]
              const float* __restrict__ xclp,   // x channels-last (SKIP)
              const float* __restrict__ bias1,
              const float* __restrict__ bias2,
              float* __restrict__ outp)
{
    constexpr int NSUB = INCH >> 5;
    constexpr int ZT   = (OUTD + 3) / 4;
    constexpr int NW   = NCH - (SKIP ? 1 : 0);
    constexpr int AS   = 36;                    // padded A row stride (floats)
    constexpr int ABUF = 256*AS;                // 9216 floats

    extern __shared__ float smem[];
    const uint32_t sb = smem_u32(smem);

    const int tid  = threadIdx.x;
    const int wid  = tid >> 5;
    const int lane = tid & 31;
    const int g    = lane >> 2;
    const int t    = lane & 3;

    const int bx = blockIdx.x, by = blockIdx.y;
    const int n  = blockIdx.z / ZT;
    const int zt = blockIdx.z % ZT;
    const int z0 = zt*4, y0 = by*4, x0 = bx*16;

    const float* inb = in + (size_t)n*IND*IND*IND*INCH;
    const float* xb  = SKIP ? (xclp + (size_t)n*28311552) : nullptr;
    const float* wb  = wtil + (size_t)n*NW*2048;
    const float* wsb = SKIP ? (wskip + (size_t)n*2048) : nullptr;

    // builder: thread tid owns A row m = tid
    const int m  = tid;
    const int gz = z0 + (m >> 6);
    const int gy = y0 + ((m >> 4) & 3);
    const int gx = x0 + (m & 15);
    const bool bvalid = (gz < OUTD) && (gy < OUTD) && (gx < OUTD);

    if (tid < 64){
        float b = bias1[tid];
        if constexpr (SKIP) b += bias2[tid];
        smem[22528 + tid] = b;
    }

    float acc[2][8][4];
    #pragma unroll
    for (int mt = 0; mt < 2; mt++)
        #pragma unroll
        for (int nt = 0; nt < 8; nt++)
            #pragma unroll
            for (int r = 0; r < 4; r++) acc[mt][nt][r] = 0.f;

    auto load_chunk = [&](int kc, int buf){
        const float* src; int dim, cs, kz, ky, kx, iho;
        const bool isSkip = SKIP && (kc == NCH - 1);
        if (isSkip){ src = xb; dim = 96; cs = 32; kz = ky = kx = 2; iho = 0; }
        else {
            int tap = kc / NSUB; iho = (kc % NSUB)*32;
            kz = tap/9; ky = (tap%9)/3; kx = tap%3;
            src = inb; dim = IND; cs = INCH;
        }
        const float* gp = bvalid
            ? (src + (((size_t)(gz+kz)*dim + (gy+ky))*dim + (gx+kx))*cs + iho)
            : src;
        const uint32_t sz = bvalid ? 16u : 0u;
        uint32_t ad = sb + (uint32_t)(buf*ABUF + m*AS)*4u;
        #pragma unroll
        for (int j = 0; j < 8; j++) cpa16(ad + j*16, gp + j*4, sz);
        const float* bs = isSkip ? wsb : (wb + (size_t)kc*2048);
        uint32_t bd = sb + (uint32_t)(2*ABUF + buf*2048)*4u + (uint32_t)tid*16u;
        cpa16(bd,          bs + tid*4,        16u);
        cpa16(bd + 4096u,  bs + 1024 + tid*4, 16u);
        CP_COMMIT();
    };

    load_chunk(0, 0);
    int buf = 0;
    const int strip = wid*32;

    #pragma unroll 1
    for (int kc = 0; kc < NCH; kc++){
        if (kc + 1 < NCH){ load_chunk(kc + 1, buf ^ 1); CP_WAIT1(); }
        else             { CP_WAIT0(); }
        __syncthreads();

        const float* A0 = smem + buf*ABUF;
        const float* B0 = smem + 2*ABUF + buf*2048;
        #pragma unroll
        for (int s = 0; s < 4; s++){
            uint32_t a[2][4];
            #pragma unroll
            for (int mt = 0; mt < 2; mt++){
                const float* ap = A0 + (strip + mt*16)*AS + s*8;
                a[mt][0] = __float_as_uint(ap[(g    )*AS + t    ]);
                a[mt][1] = __float_as_uint(ap[(g + 8)*AS + t    ]);
                a[mt][2] = __float_as_uint(ap[(g    )*AS + t + 4]);
                a[mt][3] = __float_as_uint(ap[(g + 8)*AS + t + 4]);
            }
            #pragma unroll
            for (int nt = 0; nt < 8; nt++){
                float2 bv = *(const float2*)(B0 + ((s*8 + nt)*32 + lane)*2);
                uint32_t b0 = __float_as_uint(bv.x), b1 = __float_as_uint(bv.y);
                mma8(acc[0][nt], a[0], b0, b1);
                mma8(acc[1][nt], a[1], b0, b1);
            }
        }
        __syncthreads();
        buf ^= 1;
    }

    // ---------------- epilogue ----------------
    const float* sbias = smem + 22528;
    #pragma unroll
    for (int mt = 0; mt < 2; mt++){
        #pragma unroll
        for (int half = 0; half < 2; half++){
            const int row = strip + mt*16 + g + 8*half;
            const int vz = z0 + (row >> 6);
            const int vy = y0 + ((row >> 4) & 3);
            const int vx = x0 + (row & 15);
            if (vz >= OUTD || vy >= OUTD || vx >= OUTD) continue;
            if constexpr (!SKIP){
                float* dst = outp + (((size_t)n*OUTD*OUTD*OUTD)
                           + (((size_t)vz*OUTD + vy)*OUTD + vx))*64;
                #pragma unroll
                for (int nt = 0; nt < 8; nt++){
                    const int c0 = nt*8 + 2*t;
                    float2 v;
                    v.x = tf32r(leaky(acc[mt][nt][2*half + 0] + sbias[c0]));
                    v.y = tf32r(leaky(acc[mt][nt][2*half + 1] + sbias[c0 + 1]));
                    *(float2*)(dst + c0) = v;
                }
            } else {
                const size_t plane = (size_t)OUTD*OUTD*OUTD;
                float* base = outp + (size_t)n*64*plane
                            + (((size_t)vz*OUTD + vy)*OUTD + vx);
                #pragma unroll
                for (int nt = 0; nt < 8; nt++){
                    const int c0 = nt*8 + 2*t;
                    base[(size_t)c0*plane]       = leaky(acc[mt][nt][2*half + 0] + sbias[c0]);
                    base[(size_t)(c0 + 1)*plane] = leaky(acc[mt][nt][2*half + 1] + sbias[c0 + 1]);
                }
            }
        }
    }
}

// ---------------- launch ----------------
static const int CONV_SMEM = 90368;   // 22592 floats

extern "C" void kernel_launch(void* const* d_in, const int* in_sizes, int n_in,
                              void* d_out, int out_size)
{
    (void)in_sizes; (void)n_in; (void)out_size;
    const float* x       = (const float*)d_in[0];
    const float* s       = (const float*)d_in[1];
    const float* skip_w1 = (const float*)d_in[2];
    const float* skip_b1 = (const float*)d_in[3];
    const float* skip_w2 = (const float*)d_in[4];
    const float* skip_b2 = (const float*)d_in[5];
    const float* skip_w3 = (const float*)d_in[6];
    const float* skip_b3 = (const float*)d_in[7];
    const float* skip_wc = (const float*)d_in[8];
    const float* skip_bc = (const float*)d_in[9];
    const float* c1_w1   = (const float*)d_in[10];
    const float* c1_b1   = (const float*)d_in[11];
    const float* c1_w2   = (const float*)d_in[12];
    const float* c1_b2   = (const float*)d_in[13];
    const float* c1_w3   = (const float*)d_in[14];
    const float* c1_b3   = (const float*)d_in[15];
    const float* c1_wc   = (const float*)d_in[16];
    const float* c1_bc   = (const float*)d_in[17];
    const float* c2_w1   = (const float*)d_in[18];
    const float* c2_b1   = (const float*)d_in[19];
    const float* c2_w2   = (const float*)d_in[20];
    const float* c2_b2   = (const float*)d_in[21];
    const float* c2_w3   = (const float*)d_in[22];
    const float* c2_b3   = (const float*)d_in[23];
    const float* c2_wc   = (const float*)d_in[24];
    const float* c2_bc   = (const float*)d_in[25];

    float *p_xcl, *p_h, *p_w1, *p_w2, *p_ws;
    cudaGetSymbolAddress((void**)&p_xcl, g_xcl);
    cudaGetSymbolAddress((void**)&p_h,   g_h);
    cudaGetSymbolAddress((void**)&p_w1,  g_wc1);
    cudaGetSymbolAddress((void**)&p_w2,  g_wc2);
    cudaGetSymbolAddress((void**)&p_ws,  g_wsk);

    cudaFuncSetAttribute((const void*)conv_mma<96,94,32,27,false>,
                         cudaFuncAttributeMaxDynamicSharedMemorySize, CONV_SMEM);
    cudaFuncSetAttribute((const void*)conv_mma<94,92,64,55,true>,
                         cudaFuncAttributeMaxDynamicSharedMemorySize, CONV_SMEM);

    prep_kernel<<<2, 256>>>(s, skip_w1, skip_b1, skip_w2, skip_b2, skip_w3, skip_b3,
                            skip_wc, p_ws, 64, 64, 32, 1);
    prep_kernel<<<2, 256>>>(s, c1_w1, c1_b1, c1_w2, c1_b2, c1_w3, c1_b3,
                            c1_wc, p_w1, 64, 64, 32, 27);
    prep_kernel<<<2, 256>>>(s, c2_w1, c2_b1, c2_w2, c2_b2, c2_w3, c2_b3,
                            c2_wc, p_w2, 128, 128, 64, 27);
    xconvert_kernel<<<dim3(96,96,2), 128>>>(x, p_xcl);

    // c1: xcl -> h (channels-last tf32, bias+leaky applied, tf32-rounded)
    conv_mma<96,94,32,27,false><<<dim3(6,24,48), 256, CONV_SMEM>>>(
        p_xcl, p_w1, nullptr, nullptr, c1_bc, nullptr, p_h);

    // c2 + fused skip + both biases + final leaky -> NCDHW fp32 out
    conv_mma<94,92,64,55,true><<<dim3(6,23,46), 256, CONV_SMEM>>>(
        p_h, p_w2, p_ws, p_xcl, c2_bc, skip_bc, (float*)d_out);
}

// round 6
// speedup vs baseline: 3.2018x; 1.7486x over previous
#include <cuda_runtime.h>
#include <cuda_fp16.h>
#include <cstdint>

__device__ __forceinline__ float leaky(float v){ return v > 0.f ? v : 0.01f*v; }
__device__ __forceinline__ uint32_t smem_u32(const void* p){
    uint32_t a; asm("{ .reg .u64 t; cvta.to.shared.u64 t, %1; cvt.u32.u64 %0, t; }" : "=r"(a) : "l"(p));
    return a;
}
__device__ __forceinline__ void cpa16(uint32_t dst, const void* src, uint32_t sz){
    asm volatile("cp.async.cg.shared.global [%0], [%1], 16, %2;"
                 :: "r"(dst), "l"(src), "r"(sz) : "memory");
}
#define CP_COMMIT() asm volatile("cp.async.commit_group;" ::: "memory")
#define CP_WAIT1()  asm volatile("cp.async.wait_group 1;" ::: "memory")
#define CP_WAIT0()  asm volatile("cp.async.wait_group 0;" ::: "memory")

__device__ __forceinline__ void mma16(float* c, const uint32_t* a, uint32_t b0, uint32_t b1){
    asm volatile("mma.sync.aligned.m16n8k16.row.col.f32.f16.f16.f32 "
        "{%0,%1,%2,%3}, {%4,%5,%6,%7}, {%8,%9}, {%0,%1,%2,%3};"
        : "+f"(c[0]), "+f"(c[1]), "+f"(c[2]), "+f"(c[3])
        : "r"(a[0]), "r"(a[1]), "r"(a[2]), "r"(a[3]), "r"(b0), "r"(b1));
}

// ---------------- device scratch ----------------
__device__ __align__(16) __half g_xcl[(size_t)2*96*96*96*32];   // x channels-last fp16
__device__ __align__(16) __half g_h  [(size_t)2*94*94*94*64];   // h channels-last fp16
__device__ __align__(16) __half g_wc1[2*27*2048];               // B fragments per 32-K chunk
__device__ __align__(16) __half g_wc2[2*54*2048];
__device__ __align__(16) __half g_wsk[2*2048];

// ---------------- prep: style MLP + modulate/demod + fp16 B-fragment tiles ----------------
// Fragment order (m16n8k16): per chunk, entry (s,nt,lane) -> 4 halfs:
//   W[oc][kb+2t], W[oc][kb+2t+1], W[oc][kb+2t+8], W[oc][kb+2t+9]
// with oc = nt*8+g, kb = s*16, g=lane>>2, t=lane&3.
__global__ void prep_kernel(const float* __restrict__ s,
                            const float* __restrict__ w1, const float* __restrict__ b1,
                            const float* __restrict__ w2, const float* __restrict__ b2,
                            const float* __restrict__ w3, const float* __restrict__ b3,
                            const float* __restrict__ wc, __half* __restrict__ gw,
                            int H1, int H2, int IC, int KD)
{
    const int n = blockIdx.x, tid = threadIdx.x;
    __shared__ float sv[64], a1[128], a2[128], mod[64], dem[64];
    if (tid < 64) sv[tid] = s[n*64 + tid];
    __syncthreads();
    if (tid < H1){
        float a = b1[tid];
        for (int k = 0; k < 64; k++) a += sv[k]*w1[tid*64 + k];
        a1[tid] = leaky(a);
    }
    __syncthreads();
    if (tid < H2){
        float a = b2[tid];
        for (int k = 0; k < H1; k++) a += a1[k]*w2[tid*H1 + k];
        a2[tid] = leaky(a);
    }
    __syncthreads();
    if (tid < IC){
        float a = b3[tid];
        for (int k = 0; k < H2; k++) a += a2[k]*w3[tid*H2 + k];
        mod[tid] = a;
    }
    __syncthreads();
    if (tid < 64){
        float ss = 0.f;
        for (int i = 0; i < IC; i++){
            float m = mod[i];
            const float* wp = wc + (tid*IC + i)*KD;
            for (int k = 0; k < KD; k++){ float t = wp[k]*m; ss += t*t; }
        }
        dem[tid] = rsqrtf(ss + 1e-8f);
    }
    __syncthreads();
    const int nsub = IC >> 5;
    const int total = KD * nsub * 2048;
    for (int e = tid; e < total; e += blockDim.x){
        int j    = e & 3;
        int lane = (e >> 2) & 31;
        int nt   = (e >> 7) & 7;
        int ss_  = (e >> 10) & 1;
        int c    = e >> 11;
        int g    = lane >> 2, t = lane & 3;
        int oc   = nt*8 + g;
        int kloc = ss_*16 + 2*t + (j & 1) + 8*(j >> 1);
        int tap  = c / nsub, ih = c % nsub;
        int ic   = ih*32 + kloc;
        gw[(size_t)n*total + e] = __float2half_rn(wc[(oc*IC + ic)*KD + tap] * mod[ic] * dem[oc]);
    }
}

// ---------------- x -> channels-last fp16 ----------------
__global__ void xconvert_kernel(const float* __restrict__ x, __half* __restrict__ xcl)
{
    const int y = blockIdx.x, z = blockIdx.y, n = blockIdx.z;
    __shared__ float sm[32*97];
    const float* src = x + (size_t)n*28311552 + (size_t)z*9216 + (size_t)y*96;
    for (int e = threadIdx.x; e < 32*96; e += 128){
        int ic = e / 96, xx = e % 96;
        sm[ic*97 + xx] = src[(size_t)ic*884736 + xx];
    }
    __syncthreads();
    __half* dst = xcl + (size_t)n*28311552 + ((size_t)z*96 + y)*96*32;
    for (int e = threadIdx.x; e < 32*96/2; e += 128){
        int xx = e >> 4, icp = (e & 15)*2;
        __half2 v = __floats2half2_rn(sm[icp*97 + xx], sm[(icp+1)*97 + xx]);
        *(__half2*)(dst + (size_t)xx*32 + icp) = v;
    }
}

// ---------------- implicit-GEMM conv via mma.sync fp16 (fp32 accum) ----------------
// CTA: 256 threads / 8 warps; tile M=256 voxels (4z x 4y x 16x) x N=64 oc.
// Warp strip = 32 M rows (2 x m16 frags). K chunks of 32 (tap x ic-half),
// 3-stage cp.async pipeline, one __syncthreads per chunk.
// smem bytes: A 3*256*80=61440 | B 3*4096=12288 | bias 256  => 73984
template<int IND, int OUTD, int INCH, int NCH, bool SKIP>
__global__ __launch_bounds__(256, 2)
void conv_mma(const __half* __restrict__ in,     // channels-last fp16 [n][IND^3][INCH]
              const __half* __restrict__ wtil,   // [n][NW][2048] B fragments
              const __half* __restrict__ wskip,  // [n][2048]
              const __half* __restrict__ xclp,   // x channels-last (SKIP)
              const float* __restrict__ bias1,
              const float* __restrict__ bias2,
              void* __restrict__ outp)
{
    constexpr int NSUB = INCH >> 5;
    constexpr int ZT   = (OUTD + 3) / 4;
    constexpr int NW   = NCH - (SKIP ? 1 : 0);
    constexpr int ASB  = 80;              // A row stride bytes (bank-perm 20g+t)
    constexpr int ASTG = 256*ASB;         // 20480 B per A stage
    constexpr int BOFF = 3*ASTG;          // 61440
    constexpr int BSTG = 4096;
    constexpr int BIAS = BOFF + 3*BSTG;   // 73728

    extern __shared__ __align__(16) unsigned char smem[];
    const uint32_t sb = smem_u32(smem);
    float* sbias = (float*)(smem + BIAS);

    const int tid  = threadIdx.x;
    const int lane = tid & 31;
    const int g    = lane >> 2;
    const int t    = lane & 3;
    const int strip = (tid >> 5) * 32;

    const int bx = blockIdx.x, by = blockIdx.y;
    const int n  = blockIdx.z / ZT;
    const int zt = blockIdx.z % ZT;
    const int z0 = zt*4, y0 = by*4, x0 = bx*16;

    const __half* inb = in + (size_t)n*IND*IND*IND*INCH;
    const __half* xb  = SKIP ? (xclp + (size_t)n*28311552) : nullptr;
    const __half* wb  = wtil + (size_t)n*NW*2048;
    const __half* wsb = SKIP ? (wskip + (size_t)n*2048) : nullptr;

    // builder: thread tid owns A row m = tid
    const int m  = tid;
    const int gz = z0 + (m >> 6);
    const int gy = y0 + ((m >> 4) & 3);
    const int gx = x0 + (m & 15);
    const bool bvalid = (gz < OUTD) && (gy < OUTD) && (gx < OUTD);

    if (tid < 64){
        float b = bias1[tid];
        if constexpr (SKIP) b += bias2[tid];
        sbias[tid] = b;
    }

    float acc[2][8][4];
    #pragma unroll
    for (int mt = 0; mt < 2; mt++)
        #pragma unroll
        for (int nt = 0; nt < 8; nt++)
            #pragma unroll
            for (int r = 0; r < 4; r++) acc[mt][nt][r] = 0.f;

    auto load_chunk = [&](int kc, int st){
        const __half* src; int dim, cs, kz, ky, kx, iho;
        const bool isSkip = SKIP && (kc == NCH - 1);
        if (isSkip){ src = xb; dim = 96; cs = 32; kz = ky = kx = 2; iho = 0; }
        else {
            int tap = kc / NSUB; iho = (kc % NSUB)*32;
            kz = tap/9; ky = (tap%9)/3; kx = tap%3;
            src = inb; dim = IND; cs = INCH;
        }
        const __half* gp = bvalid
            ? (src + (((size_t)(gz+kz)*dim + (gy+ky))*dim + (gx+kx))*cs + iho)
            : src;
        const uint32_t sz = bvalid ? 16u : 0u;
        uint32_t ad = sb + (uint32_t)(st*ASTG + m*ASB);
        #pragma unroll
        for (int j = 0; j < 4; j++) cpa16(ad + j*16, gp + j*8, sz);
        const __half* bs = isSkip ? wsb : (wb + (size_t)kc*2048);
        cpa16(sb + (uint32_t)(BOFF + st*BSTG) + (uint32_t)tid*16u, bs + tid*8, 16u);
        CP_COMMIT();
    };

    load_chunk(0, 0);
    load_chunk(1, 1);
    int st = 0;

    #pragma unroll 1
    for (int kc = 0; kc < NCH; kc++){
        if (kc + 1 < NCH) CP_WAIT1(); else CP_WAIT0();
        __syncthreads();
        if (kc + 2 < NCH){
            int st2 = st + 2; if (st2 >= 3) st2 -= 3;
            load_chunk(kc + 2, st2);
        }
        const unsigned char* A0 = smem + st*ASTG;
        const unsigned char* B0 = smem + BOFF + st*BSTG;
        #pragma unroll
        for (int s = 0; s < 2; s++){
            uint32_t a[2][4];
            #pragma unroll
            for (int mt = 0; mt < 2; mt++){
                const unsigned char* ap = A0 + (strip + mt*16 + g)*ASB + s*32 + t*4;
                a[mt][0] = *(const uint32_t*)(ap);
                a[mt][1] = *(const uint32_t*)(ap + 8*ASB);
                a[mt][2] = *(const uint32_t*)(ap + 16);
                a[mt][3] = *(const uint32_t*)(ap + 8*ASB + 16);
            }
            #pragma unroll
            for (int nt = 0; nt < 8; nt++){
                uint2 bv = *(const uint2*)(B0 + (((s*8 + nt)*32 + lane) << 3));
                mma16(acc[0][nt], a[0], bv.x, bv.y);
                mma16(acc[1][nt], a[1], bv.x, bv.y);
            }
        }
        st = (st == 2) ? 0 : st + 1;
    }

    // ---------------- epilogue ----------------
    #pragma unroll
    for (int mt = 0; mt < 2; mt++){
        #pragma unroll
        for (int half = 0; half < 2; half++){
            const int row = strip + mt*16 + g + 8*half;
            const int vz = z0 + (row >> 6);
            const int vy = y0 + ((row >> 4) & 3);
            const int vx = x0 + (row & 15);
            if (vz >= OUTD || vy >= OUTD || vx >= OUTD) continue;
            if constexpr (!SKIP){
                __half* dst = (__half*)outp + (((size_t)n*OUTD*OUTD*OUTD)
                            + (((size_t)vz*OUTD + vy)*OUTD + vx))*64;
                #pragma unroll
                for (int nt = 0; nt < 8; nt++){
                    const int c0 = nt*8 + 2*t;
                    float v0 = leaky(acc[mt][nt][2*half + 0] + sbias[c0]);
                    float v1 = leaky(acc[mt][nt][2*half + 1] + sbias[c0 + 1]);
                    *(__half2*)(dst + c0) = __floats2half2_rn(v0, v1);
                }
            } else {
                const size_t plane = (size_t)OUTD*OUTD*OUTD;
                float* base = (float*)outp + (size_t)n*64*plane
                            + (((size_t)vz*OUTD + vy)*OUTD + vx);
                #pragma unroll
                for (int nt = 0; nt < 8; nt++){
                    const int c0 = nt*8 + 2*t;
                    base[(size_t)c0*plane]       = leaky(acc[mt][nt][2*half + 0] + sbias[c0]);
                    base[(size_t)(c0 + 1)*plane] = leaky(acc[mt][nt][2*half + 1] + sbias[c0 + 1]);
                }
            }
        }
    }
}

// ---------------- launch ----------------
static const int CONV_SMEM = 73984;

extern "C" void kernel_launch(void* const* d_in, const int* in_sizes, int n_in,
                              void* d_out, int out_size)
{
    (void)in_sizes; (void)n_in; (void)out_size;
    const float* x       = (const float*)d_in[0];
    const float* s       = (const float*)d_in[1];
    const float* skip_w1 = (const float*)d_in[2];
    const float* skip_b1 = (const float*)d_in[3];
    const float* skip_w2 = (const float*)d_in[4];
    const float* skip_b2 = (const float*)d_in[5];
    const float* skip_w3 = (const float*)d_in[6];
    const float* skip_b3 = (const float*)d_in[7];
    const float* skip_wc = (const float*)d_in[8];
    const float* skip_bc = (const float*)d_in[9];
    const float* c1_w1   = (const float*)d_in[10];
    const float* c1_b1   = (const float*)d_in[11];
    const float* c1_w2   = (const float*)d_in[12];
    const float* c1_b2   = (const float*)d_in[13];
    const float* c1_w3   = (const float*)d_in[14];
    const float* c1_b3   = (const float*)d_in[15];
    const float* c1_wc   = (const float*)d_in[16];
    const float* c1_bc   = (const float*)d_in[17];
    const float* c2_w1   = (const float*)d_in[18];
    const float* c2_b1   = (const float*)d_in[19];
    const float* c2_w2   = (const float*)d_in[20];
    const float* c2_b2   = (const float*)d_in[21];
    const float* c2_w3   = (const float*)d_in[22];
    const float* c2_b3   = (const float*)d_in[23];
    const float* c2_wc   = (const float*)d_in[24];
    const float* c2_bc   = (const float*)d_in[25];

    __half *p_xcl, *p_h, *p_w1, *p_w2, *p_ws;
    cudaGetSymbolAddress((void**)&p_xcl, g_xcl);
    cudaGetSymbolAddress((void**)&p_h,   g_h);
    cudaGetSymbolAddress((void**)&p_w1,  g_wc1);
    cudaGetSymbolAddress((void**)&p_w2,  g_wc2);
    cudaGetSymbolAddress((void**)&p_ws,  g_wsk);

    cudaFuncSetAttribute((const void*)conv_mma<96,94,32,27,false>,
                         cudaFuncAttributeMaxDynamicSharedMemorySize, CONV_SMEM);
    cudaFuncSetAttribute((const void*)conv_mma<94,92,64,55,true>,
                         cudaFuncAttributeMaxDynamicSharedMemorySize, CONV_SMEM);

    prep_kernel<<<2, 256>>>(s, skip_w1, skip_b1, skip_w2, skip_b2, skip_w3, skip_b3,
                            skip_wc, p_ws, 64, 64, 32, 1);
    prep_kernel<<<2, 256>>>(s, c1_w1, c1_b1, c1_w2, c1_b2, c1_w3, c1_b3,
                            c1_wc, p_w1, 64, 64, 32, 27);
    prep_kernel<<<2, 256>>>(s, c2_w1, c2_b1, c2_w2, c2_b2, c2_w3, c2_b3,
                            c2_wc, p_w2, 128, 128, 64, 27);
    xconvert_kernel<<<dim3(96,96,2), 128>>>(x, p_xcl);

    // c1: xcl -> h (channels-last fp16, bias+leaky applied)
    conv_mma<96,94,32,27,false><<<dim3(6,24,48), 256, CONV_SMEM>>>(
        p_xcl, p_w1, nullptr, nullptr, c1_bc, nullptr, (void*)p_h);

    // c2 + fused skip + both biases + final leaky -> NCDHW fp32 out
    conv_mma<94,92,64,55,true><<<dim3(6,23,46), 256, CONV_SMEM>>>(
        p_h, p_w2, p_ws, p_xcl, c2_bc, skip_bc, d_out);
}

// round 7
// speedup vs baseline: 3.6233x; 1.1316x over previous
#include <cuda_runtime.h>
#include <cuda_fp16.h>
#include <cstdint>

__device__ __forceinline__ float leaky(float v){ return v > 0.f ? v : 0.01f*v; }
__device__ __forceinline__ uint32_t smem_u32(const void* p){
    uint32_t a; asm("{ .reg .u64 t; cvta.to.shared.u64 t, %1; cvt.u32.u64 %0, t; }" : "=r"(a) : "l"(p));
    return a;
}
__device__ __forceinline__ void cpa16(uint32_t dst, const void* src, uint32_t sz){
    asm volatile("cp.async.cg.shared.global [%0], [%1], 16, %2;"
                 :: "r"(dst), "l"(src), "r"(sz) : "memory");
}
#define CP_COMMIT() asm volatile("cp.async.commit_group;" ::: "memory")
#define CP_WAIT1()  asm volatile("cp.async.wait_group 1;" ::: "memory")
#define CP_WAIT0()  asm volatile("cp.async.wait_group 0;" ::: "memory")

__device__ __forceinline__ void mma16(float* c, const uint32_t* a, uint32_t b0, uint32_t b1){
    asm volatile("mma.sync.aligned.m16n8k16.row.col.f32.f16.f16.f32 "
        "{%0,%1,%2,%3}, {%4,%5,%6,%7}, {%8,%9}, {%0,%1,%2,%3};"
        : "+f"(c[0]), "+f"(c[1]), "+f"(c[2]), "+f"(c[3])
        : "r"(a[0]), "r"(a[1]), "r"(a[2]), "r"(a[3]), "r"(b0), "r"(b1));
}
__device__ __forceinline__ void ldmA(uint32_t* a, uint32_t addr){
    asm volatile("ldmatrix.sync.aligned.m8n8.x4.shared.b16 {%0,%1,%2,%3}, [%4];"
        : "=r"(a[0]), "=r"(a[1]), "=r"(a[2]), "=r"(a[3]) : "r"(addr));
}

// ---------------- device scratch ----------------
__device__ __align__(16) __half g_xcl[(size_t)2*96*96*96*32];   // x channels-last fp16
__device__ __align__(16) __half g_h  [(size_t)2*94*94*94*64];   // h channels-last fp16
__device__ __align__(16) __half g_wc1[2*27*2048];               // B fragments per 32-K chunk
__device__ __align__(16) __half g_wc2[2*54*2048];
__device__ __align__(16) __half g_wsk[2*2048];

// ---------------- prep: style MLP + modulate/demod + fp16 B-fragment tiles ----------------
// B layout per chunk: entry ((nt*32 + lane)*8 + j) halfs, j in 0..7:
//   s = j>>2, kloc = s*16 + 2t + (j&1) + 8*((j>>1)&1), oc = nt*8 + (lane>>2), t = lane&3
__global__ void prep_kernel(const float* __restrict__ s,
                            const float* __restrict__ w1, const float* __restrict__ b1,
                            const float* __restrict__ w2, const float* __restrict__ b2,
                            const float* __restrict__ w3, const float* __restrict__ b3,
                            const float* __restrict__ wc, __half* __restrict__ gw,
                            int H1, int H2, int IC, int KD)
{
    const int n = blockIdx.x, tid = threadIdx.x;
    __shared__ float sv[64], a1[128], a2[128], mod[64], dem[64];
    if (tid < 64) sv[tid] = s[n*64 + tid];
    __syncthreads();
    if (tid < H1){
        float a = b1[tid];
        for (int k = 0; k < 64; k++) a += sv[k]*w1[tid*64 + k];
        a1[tid] = leaky(a);
    }
    __syncthreads();
    if (tid < H2){
        float a = b2[tid];
        for (int k = 0; k < H1; k++) a += a1[k]*w2[tid*H1 + k];
        a2[tid] = leaky(a);
    }
    __syncthreads();
    if (tid < IC){
        float a = b3[tid];
        for (int k = 0; k < H2; k++) a += a2[k]*w3[tid*H2 + k];
        mod[tid] = a;
    }
    __syncthreads();
    if (tid < 64){
        float ss = 0.f;
        for (int i = 0; i < IC; i++){
            float m = mod[i];
            const float* wp = wc + (tid*IC + i)*KD;
            for (int k = 0; k < KD; k++){ float t = wp[k]*m; ss += t*t; }
        }
        dem[tid] = rsqrtf(ss + 1e-8f);
    }
    __syncthreads();
    const int nsub = IC >> 5;
    const int total = KD * nsub * 2048;
    for (int e = tid; e < total; e += blockDim.x){
        int j    = e & 7;
        int lane = (e >> 3) & 31;
        int nt   = (e >> 8) & 7;
        int c    = e >> 11;
        int g    = lane >> 2, t = lane & 3;
        int oc   = nt*8 + g;
        int kloc = (j >> 2)*16 + 2*t + (j & 1) + 8*((j >> 1) & 1);
        int tap  = c / nsub, ih = c % nsub;
        int ic   = ih*32 + kloc;
        gw[(size_t)n*total + e] = __float2half_rn(wc[(oc*IC + ic)*KD + tap] * mod[ic] * dem[oc]);
    }
}

// ---------------- x -> channels-last fp16 ----------------
__global__ void xconvert_kernel(const float* __restrict__ x, __half* __restrict__ xcl)
{
    const int y = blockIdx.x, z = blockIdx.y, n = blockIdx.z;
    __shared__ float sm[32*97];
    const float* src = x + (size_t)n*28311552 + (size_t)z*9216 + (size_t)y*96;
    for (int e = threadIdx.x; e < 32*96; e += 128){
        int ic = e / 96, xx = e % 96;
        sm[ic*97 + xx] = src[(size_t)ic*884736 + xx];
    }
    __syncthreads();
    __half* dst = xcl + (size_t)n*28311552 + ((size_t)z*96 + y)*96*32;
    for (int e = threadIdx.x; e < 32*96/2; e += 128){
        int xx = e >> 4, icp = (e & 15)*2;
        __half2 v = __floats2half2_rn(sm[icp*97 + xx], sm[(icp+1)*97 + xx]);
        *(__half2*)(dst + (size_t)xx*32 + icp) = v;
    }
}

// ---------------- implicit-GEMM conv via mma.sync fp16 (fp32 accum) ----------------
// CTA: 128 threads / 4 warps; tile M=256 voxels (4z x 4y x 16x) x N=64 oc.
// Warp = 64 M rows (4 x m16 frags via ldmatrix) x 64 oc (8 n-tiles).
// K chunks of 32, 3-stage cp.async pipeline, one __syncthreads per chunk.
// smem bytes: A 3*256*80=61440 | B 3*4096=12288 | bias 256  => 73984
template<int IND, int OUTD, int INCH, int NCH, bool SKIP>
__global__ __launch_bounds__(128, 2)
void conv_mma(const __half* __restrict__ in,     // channels-last fp16 [n][IND^3][INCH]
              const __half* __restrict__ wtil,   // [n][NW][2048] B fragments
              const __half* __restrict__ wskip,  // [n][2048]
              const __half* __restrict__ xclp,   // x channels-last (SKIP)
              const float* __restrict__ bias1,
              const float* __restrict__ bias2,
              void* __restrict__ outp)
{
    constexpr int NSUB = INCH >> 5;
    constexpr int ZT   = (OUTD + 3) / 4;
    constexpr int NW   = NCH - (SKIP ? 1 : 0);
    constexpr int ASB  = 80;              // A row stride bytes
    constexpr int ASTG = 256*ASB;         // 20480 B per A stage
    constexpr int BOFF = 3*ASTG;          // 61440
    constexpr int BSTG = 4096;
    constexpr int BIAS = BOFF + 3*BSTG;   // 73728

    extern __shared__ __align__(16) unsigned char smem[];
    const uint32_t sb = smem_u32(smem);
    float* sbias = (float*)(smem + BIAS);

    const int tid  = threadIdx.x;
    const int lane = tid & 31;
    const int g    = lane >> 2;
    const int t    = lane & 3;
    const int strip = (tid >> 5) * 64;     // warp's 64-row strip

    const int bx = blockIdx.x, by = blockIdx.y;
    const int n  = blockIdx.z / ZT;
    const int zt = blockIdx.z % ZT;
    const int z0 = zt*4, y0 = by*4, x0 = bx*16;

    const __half* inb = in + (size_t)n*IND*IND*IND*INCH;
    const __half* xb  = SKIP ? (xclp + (size_t)n*28311552) : nullptr;
    const __half* wb  = wtil + (size_t)n*NW*2048;
    const __half* wsb = SKIP ? (wskip + (size_t)n*2048) : nullptr;

    // builder rows: thread owns rows tid and tid+128
    const int m1 = tid, m2 = tid + 128;
    const int gz1 = z0 + (m1 >> 6), gy1 = y0 + ((m1 >> 4) & 3), gx1 = x0 + (m1 & 15);
    const int gz2 = z0 + (m2 >> 6), gy2 = y0 + ((m2 >> 4) & 3), gx2 = x0 + (m2 & 15);
    const bool bv1 = (gz1 < OUTD) && (gy1 < OUTD) && (gx1 < OUTD);
    const bool bv2 = (gz2 < OUTD) && (gy2 < OUTD) && (gx2 < OUTD);

    if (tid < 64){
        float b = bias1[tid];
        if constexpr (SKIP) b += bias2[tid];
        sbias[tid] = b;
    }

    float acc[4][8][4];
    #pragma unroll
    for (int mt = 0; mt < 4; mt++)
        #pragma unroll
        for (int nt = 0; nt < 8; nt++)
            #pragma unroll
            for (int r = 0; r < 4; r++) acc[mt][nt][r] = 0.f;

    auto load_chunk = [&](int kc, int st){
        const __half* src; int dim, cs, kz, ky, kx, iho;
        const bool isSkip = SKIP && (kc == NCH - 1);
        if (isSkip){ src = xb; dim = 96; cs = 32; kz = ky = kx = 2; iho = 0; }
        else {
            int tap = kc / NSUB; iho = (kc % NSUB)*32;
            kz = tap/9; ky = (tap%9)/3; kx = tap%3;
            src = inb; dim = IND; cs = INCH;
        }
        const __half* gp1 = bv1
            ? (src + (((size_t)(gz1+kz)*dim + (gy1+ky))*dim + (gx1+kx))*cs + iho) : src;
        const __half* gp2 = bv2
            ? (src + (((size_t)(gz2+kz)*dim + (gy2+ky))*dim + (gx2+kx))*cs + iho) : src;
        const uint32_t sz1 = bv1 ? 16u : 0u;
        const uint32_t sz2 = bv2 ? 16u : 0u;
        uint32_t ad1 = sb + (uint32_t)(st*ASTG + m1*ASB);
        uint32_t ad2 = sb + (uint32_t)(st*ASTG + m2*ASB);
        #pragma unroll
        for (int j = 0; j < 4; j++){
            cpa16(ad1 + j*16, gp1 + j*8, sz1);
            cpa16(ad2 + j*16, gp2 + j*8, sz2);
        }
        const __half* bs = isSkip ? wsb : (wb + (size_t)kc*2048);
        uint32_t bd = sb + (uint32_t)(BOFF + st*BSTG) + (uint32_t)tid*16u;
        cpa16(bd,          bs + tid*8,        16u);
        cpa16(bd + 2048u,  bs + 1024 + tid*8, 16u);
        CP_COMMIT();
    };

    load_chunk(0, 0);
    load_chunk(1, 1);
    int st = 0;

    #pragma unroll 1
    for (int kc = 0; kc < NCH; kc++){
        if (kc + 1 < NCH) CP_WAIT1(); else CP_WAIT0();
        __syncthreads();
        if (kc + 2 < NCH){
            int st2 = st + 2; if (st2 >= 3) st2 -= 3;
            load_chunk(kc + 2, st2);
        }
        const uint32_t A0 = sb + (uint32_t)(st*ASTG);
        const unsigned char* B0 = smem + BOFF + st*BSTG;

        // A fragments: 4 m-tiles x 2 k-steps via ldmatrix.x4
        uint32_t a[2][4][4];
        const uint32_t arow = A0 + (uint32_t)((strip + (lane & 15))*ASB + ((lane >> 4) << 4));
        #pragma unroll
        for (int s = 0; s < 2; s++)
            #pragma unroll
            for (int mt = 0; mt < 4; mt++)
                ldmA(a[s][mt], arow + (uint32_t)(mt*16*ASB + s*32));

        #pragma unroll
        for (int nt = 0; nt < 8; nt++){
            uint4 bv = *(const uint4*)(B0 + ((nt*32 + lane) << 4));
            #pragma unroll
            for (int mt = 0; mt < 4; mt++){
                mma16(acc[mt][nt], a[0][mt], bv.x, bv.y);
                mma16(acc[mt][nt], a[1][mt], bv.z, bv.w);
            }
        }
        st = (st == 2) ? 0 : st + 1;
    }

    // ---------------- epilogue ----------------
    #pragma unroll
    for (int mt = 0; mt < 4; mt++){
        #pragma unroll
        for (int half = 0; half < 2; half++){
            const int row = strip + mt*16 + g + 8*half;
            const int vz = z0 + (row >> 6);
            const int vy = y0 + ((row >> 4) & 3);
            const int vx = x0 + (row & 15);
            if (vz >= OUTD || vy >= OUTD || vx >= OUTD) continue;
            if constexpr (!SKIP){
                __half* dst = (__half*)outp + (((size_t)n*OUTD*OUTD*OUTD)
                            + (((size_t)vz*OUTD + vy)*OUTD + vx))*64;
                #pragma unroll
                for (int nt = 0; nt < 8; nt++){
                    const int c0 = nt*8 + 2*t;
                    float v0 = leaky(acc[mt][nt][2*half + 0] + sbias[c0]);
                    float v1 = leaky(acc[mt][nt][2*half + 1] + sbias[c0 + 1]);
                    *(__half2*)(dst + c0) = __floats2half2_rn(v0, v1);
                }
            } else {
                const size_t plane = (size_t)OUTD*OUTD*OUTD;
                float* base = (float*)outp + (size_t)n*64*plane
                            + (((size_t)vz*OUTD + vy)*OUTD + vx);
                #pragma unroll
                for (int nt = 0; nt < 8; nt++){
                    const int c0 = nt*8 + 2*t;
                    base[(size_t)c0*plane]       = leaky(acc[mt][nt][2*half + 0] + sbias[c0]);
                    base[(size_t)(c0 + 1)*plane] = leaky(acc[mt][nt][2*half + 1] + sbias[c0 + 1]);
                }
            }
        }
    }
}

// ---------------- launch ----------------
static const int CONV_SMEM = 73984;

extern "C" void kernel_launch(void* const* d_in, const int* in_sizes, int n_in,
                              void* d_out, int out_size)
{
    (void)in_sizes; (void)n_in; (void)out_size;
    const float* x       = (const float*)d_in[0];
    const float* s       = (const float*)d_in[1];
    const float* skip_w1 = (const float*)d_in[2];
    const float* skip_b1 = (const float*)d_in[3];
    const float* skip_w2 = (const float*)d_in[4];
    const float* skip_b2 = (const float*)d_in[5];
    const float* skip_w3 = (const float*)d_in[6];
    const float* skip_b3 = (const float*)d_in[7];
    const float* skip_wc = (const float*)d_in[8];
    const float* skip_bc = (const float*)d_in[9];
    const float* c1_w1   = (const float*)d_in[10];
    const float* c1_b1   = (const float*)d_in[11];
    const float* c1_w2   = (const float*)d_in[12];
    const float* c1_b2   = (const float*)d_in[13];
    const float* c1_w3   = (const float*)d_in[14];
    const float* c1_b3   = (const float*)d_in[15];
    const float* c1_wc   = (const float*)d_in[16];
    const float* c1_bc   = (const float*)d_in[17];
    const float* c2_w1   = (const float*)d_in[18];
    const float* c2_b1   = (const float*)d_in[19];
    const float* c2_w2   = (const float*)d_in[20];
    const float* c2_b2   = (const float*)d_in[21];
    const float* c2_w3   = (const float*)d_in[22];
    const float* c2_b3   = (const float*)d_in[23];
    const float* c2_wc   = (const float*)d_in[24];
    const float* c2_bc   = (const float*)d_in[25];

    __half *p_xcl, *p_h, *p_w1, *p_w2, *p_ws;
    cudaGetSymbolAddress((void**)&p_xcl, g_xcl);
    cudaGetSymbolAddress((void**)&p_h,   g_h);
    cudaGetSymbolAddress((void**)&p_w1,  g_wc1);
    cudaGetSymbolAddress((void**)&p_w2,  g_wc2);
    cudaGetSymbolAddress((void**)&p_ws,  g_wsk);

    cudaFuncSetAttribute((const void*)conv_mma<96,94,32,27,false>,
                         cudaFuncAttributeMaxDynamicSharedMemorySize, CONV_SMEM);
    cudaFuncSetAttribute((const void*)conv_mma<94,92,64,55,true>,
                         cudaFuncAttributeMaxDynamicSharedMemorySize, CONV_SMEM);

    prep_kernel<<<2, 256>>>(s, skip_w1, skip_b1, skip_w2, skip_b2, skip_w3, skip_b3,
                            skip_wc, p_ws, 64, 64, 32, 1);
    prep_kernel<<<2, 256>>>(s, c1_w1, c1_b1, c1_w2, c1_b2, c1_w3, c1_b3,
                            c1_wc, p_w1, 64, 64, 32, 27);
    prep_kernel<<<2, 256>>>(s, c2_w1, c2_b1, c2_w2, c2_b2, c2_w3, c2_b3,
                            c2_wc, p_w2, 128, 128, 64, 27);
    xconvert_kernel<<<dim3(96,96,2), 128>>>(x, p_xcl);

    // c1: xcl -> h (channels-last fp16, bias+leaky applied)
    conv_mma<96,94,32,27,false><<<dim3(6,24,48), 128, CONV_SMEM>>>(
        p_xcl, p_w1, nullptr, nullptr, c1_bc, nullptr, (void*)p_h);

    // c2 + fused skip + both biases + final leaky -> NCDHW fp32 out
    conv_mma<94,92,64,55,true><<<dim3(6,23,46), 128, CONV_SMEM>>>(
        p_h, p_w2, p_ws, p_xcl, c2_bc, skip_bc, d_out);
}

// round 8
// speedup vs baseline: 6.2904x; 1.7361x over previous
#include <cuda_runtime.h>
#include <cuda_fp16.h>
#include <cstdint>

__device__ __forceinline__ float leaky(float v){ return v > 0.f ? v : 0.01f*v; }
__device__ __forceinline__ uint32_t smem_u32(const void* p){
    uint32_t a; asm("{ .reg .u64 t; cvta.to.shared.u64 t, %1; cvt.u32.u64 %0, t; }" : "=r"(a) : "l"(p));
    return a;
}
__device__ __forceinline__ void cpa16(uint32_t dst, const void* src, uint32_t sz){
    asm volatile("cp.async.cg.shared.global [%0], [%1], 16, %2;"
                 :: "r"(dst), "l"(src), "r"(sz) : "memory");
}
#define CP_COMMIT() asm volatile("cp.async.commit_group;" ::: "memory")
#define CP_WAIT1()  asm volatile("cp.async.wait_group 1;" ::: "memory")
#define CP_WAIT0()  asm volatile("cp.async.wait_group 0;" ::: "memory")

__device__ __forceinline__ void mma16(float* c, const uint32_t* a, uint32_t b0, uint32_t b1){
    asm volatile("mma.sync.aligned.m16n8k16.row.col.f32.f16.f16.f32 "
        "{%0,%1,%2,%3}, {%4,%5,%6,%7}, {%8,%9}, {%0,%1,%2,%3};"
        : "+f"(c[0]), "+f"(c[1]), "+f"(c[2]), "+f"(c[3])
        : "r"(a[0]), "r"(a[1]), "r"(a[2]), "r"(a[3]), "r"(b0), "r"(b1));
}
__device__ __forceinline__ void ldmA(uint32_t* a, uint32_t addr){
    asm volatile("ldmatrix.sync.aligned.m8n8.x4.shared.b16 {%0,%1,%2,%3}, [%4];"
        : "=r"(a[0]), "=r"(a[1]), "=r"(a[2]), "=r"(a[3]) : "r"(addr));
}

// ---------------- device scratch ----------------
__device__ __align__(16) __half g_xcl[(size_t)2*96*96*96*32];   // x channels-last fp16
__device__ __align__(16) __half g_h  [(size_t)2*94*94*94*64];   // h channels-last fp16
__device__ __align__(16) __half g_wc1[2*27*2048];               // B fragments per 32-K chunk
__device__ __align__(16) __half g_wc2[2*54*2048];
__device__ __align__(16) __half g_wsk[2*2048];

// ---------------- prep: style MLP + modulate/demod + fp16 B-fragment tiles ----------------
// B layout per chunk: entry ((nt*32 + lane)*8 + j) halfs, j in 0..7:
//   s = j>>2, kloc = s*16 + 2t + (j&1) + 8*((j>>1)&1), oc = nt*8 + (lane>>2), t = lane&3
__global__ void prep_kernel(const float* __restrict__ s,
                            const float* __restrict__ w1, const float* __restrict__ b1,
                            const float* __restrict__ w2, const float* __restrict__ b2,
                            const float* __restrict__ w3, const float* __restrict__ b3,
                            const float* __restrict__ wc, __half* __restrict__ gw,
                            int H1, int H2, int IC, int KD)
{
    const int n = blockIdx.x, tid = threadIdx.x;
    __shared__ float sv[64], a1[128], a2[128], mod[64], dem[64];
    if (tid < 64) sv[tid] = s[n*64 + tid];
    __syncthreads();
    if (tid < H1){
        float a = b1[tid];
        for (int k = 0; k < 64; k++) a += sv[k]*w1[tid*64 + k];
        a1[tid] = leaky(a);
    }
    __syncthreads();
    if (tid < H2){
        float a = b2[tid];
        for (int k = 0; k < H1; k++) a += a1[k]*w2[tid*H1 + k];
        a2[tid] = leaky(a);
    }
    __syncthreads();
    if (tid < IC){
        float a = b3[tid];
        for (int k = 0; k < H2; k++) a += a2[k]*w3[tid*H2 + k];
        mod[tid] = a;
    }
    __syncthreads();
    if (tid < 64){
        float ss = 0.f;
        for (int i = 0; i < IC; i++){
            float m = mod[i];
            const float* wp = wc + (tid*IC + i)*KD;
            for (int k = 0; k < KD; k++){ float t = wp[k]*m; ss += t*t; }
        }
        dem[tid] = rsqrtf(ss + 1e-8f);
    }
    __syncthreads();
    const int nsub = IC >> 5;
    const int total = KD * nsub * 2048;
    for (int e = tid; e < total; e += blockDim.x){
        int j    = e & 7;
        int lane = (e >> 3) & 31;
        int nt   = (e >> 8) & 7;
        int c    = e >> 11;
        int g    = lane >> 2, t = lane & 3;
        int oc   = nt*8 + g;
        int kloc = (j >> 2)*16 + 2*t + (j & 1) + 8*((j >> 1) & 1);
        int tap  = c / nsub, ih = c % nsub;
        int ic   = ih*32 + kloc;
        gw[(size_t)n*total + e] = __float2half_rn(wc[(oc*IC + ic)*KD + tap] * mod[ic] * dem[oc]);
    }
}

// ---------------- x -> channels-last fp16 ----------------
__global__ void xconvert_kernel(const float* __restrict__ x, __half* __restrict__ xcl)
{
    const int y = blockIdx.x, z = blockIdx.y, n = blockIdx.z;
    __shared__ float sm[32*97];
    const float* src = x + (size_t)n*28311552 + (size_t)z*9216 + (size_t)y*96;
    for (int e = threadIdx.x; e < 32*96; e += 128){
        int ic = e / 96, xx = e % 96;
        sm[ic*97 + xx] = src[(size_t)ic*884736 + xx];
    }
    __syncthreads();
    __half* dst = xcl + (size_t)n*28311552 + ((size_t)z*96 + y)*96*32;
    for (int e = threadIdx.x; e < 32*96/2; e += 128){
        int xx = e >> 4, icp = (e & 15)*2;
        __half2 v = __floats2half2_rn(sm[icp*97 + xx], sm[(icp+1)*97 + xx]);
        *(__half2*)(dst + (size_t)xx*32 + icp) = v;
    }
}

// ---------------- implicit-GEMM conv: A-resident halo, mma.sync fp16 ----------------
// CTA: 128 threads / 4 warps; tile M=256 voxels (4z x 4y x 16x) x N=64 oc.
// Input halo (6x6x18 voxels, channels-last, slot-swizzled) loaded ONCE into smem;
// ldmatrix per-lane row addressing does the im2col shift. Only B streams per chunk.
template<int IND, int OUTD, int INCH, int NCH, bool SKIP>
__global__ __launch_bounds__(128, 2)
void conv_mma(const __half* __restrict__ in,     // channels-last fp16 [n][IND^3][INCH]
              const __half* __restrict__ wtil,   // [n][NW][2048] B fragments
              const __half* __restrict__ wskip,  // [n][2048]
              const __half* __restrict__ xclp,   // x channels-last (SKIP)
              const float* __restrict__ bias1,
              const float* __restrict__ bias2,
              void* __restrict__ outp)
{
    constexpr int NSUB = INCH >> 5;
    constexpr int ZT   = (OUTD + 3) / 4;
    constexpr int CHB  = INCH * 2;          // bytes per voxel row (64 or 128)
    constexpr int P    = CHB / 16;          // 16B pieces per voxel (4 or 8)
    constexpr int HALO = 648 * CHB;         // 6*6*18 voxels
    constexpr int SKT  = SKIP ? 16384 : 0;  // 256 vox * 64B
    constexpr int BOFF = HALO + SKT;
    constexpr int BIAS = BOFF + 3*4096;

    extern __shared__ __align__(16) unsigned char smem[];
    const uint32_t sb = smem_u32(smem);
    float* sbias = (float*)(smem + BIAS);

    const int tid  = threadIdx.x;
    const int lane = tid & 31;
    const int g    = lane >> 2;
    const int t    = lane & 3;
    const int strip = (tid >> 5) * 64;

    const int bx = blockIdx.x, by = blockIdx.y;
    const int n  = blockIdx.z / ZT;
    const int zt = blockIdx.z % ZT;
    const int z0 = zt*4, y0 = by*4, x0 = bx*16;

    const __half* inb = in + (size_t)n*IND*IND*IND*INCH;
    const __half* xb  = SKIP ? (xclp + (size_t)n*28311552) : nullptr;
    const __half* wb  = wtil + (size_t)n*(NCH - (SKIP?1:0))*2048;
    const __half* wsb = SKIP ? (wskip + (size_t)n*2048) : nullptr;

    if (tid < 64){
        float b = bias1[tid];
        if constexpr (SKIP) b += bias2[tid];
        sbias[tid] = b;
    }

    // ---- one-time halo load (slot-swizzled channels-last) ----
    {
        constexpr int TOT = 648 * P;
        #pragma unroll 4
        for (int e = tid; e < TOT; e += 128){
            int vox = e / P, j = e % P;
            int hx = vox % 18, hy = (vox/18) % 6, hz = vox/108;
            bool v = (z0+hz < IND) && (y0+hy < IND) && (x0+hx < IND);
            int key = (INCH == 64) ? (hx & 7) : ((hx >> 1) & 3);
            uint32_t dst = sb + (uint32_t)(vox*CHB + ((j ^ key) << 4));
            const __half* src = inb + (((size_t)(z0+hz)*IND + (y0+hy))*IND + (x0+hx))*INCH + j*8;
            cpa16(dst, src, v ? 16u : 0u);
        }
    }
    if constexpr (SKIP){
        #pragma unroll 2
        for (int e = tid; e < 1024; e += 128){
            int vox = e >> 2, j = e & 3;
            int dx = vox & 15, dy = (vox >> 4) & 3, dz = vox >> 6;
            bool v = (z0+2+dz < 96) && (y0+2+dy < 96) && (x0+2+dx < 96);
            int key = (dx >> 1) & 3;
            uint32_t dst = sb + (uint32_t)(HALO + vox*64 + ((j ^ key) << 4));
            const __half* src = xb + (((size_t)(z0+2+dz)*96 + (y0+2+dy))*96 + (x0+2+dx))*32 + j*8;
            cpa16(dst, src, v ? 16u : 0u);
        }
    }

    auto loadB = [&](int kc, int st){
        const bool isSkip = SKIP && (kc == NCH - 1);
        const __half* bs = isSkip ? wsb : (wb + (size_t)kc*2048);
        uint32_t bd = sb + (uint32_t)(BOFF + st*4096) + (uint32_t)tid*16u;
        cpa16(bd,         bs + tid*8,        16u);
        cpa16(bd + 2048u, bs + 1024 + tid*8, 16u);
    };

    loadB(0, 0); CP_COMMIT();        // group0: halo (+skip) + B0
    loadB(1, 1); CP_COMMIT();        // group1: B1

    // per-lane ldmatrix row identity: lane -> (matrix row r, k-half kh)
    const int r  = ((lane >> 3) & 1)*8 + (lane & 7);
    const int kh = (lane >> 4) & 1;
    int dzm[4], dym[4], dxm[4];
    #pragma unroll
    for (int mt = 0; mt < 4; mt++){
        int m = strip + mt*16 + r;
        dzm[mt] = m >> 6; dym[mt] = (m >> 4) & 3; dxm[mt] = m & 15;
    }

    float acc[4][8][4];
    #pragma unroll
    for (int mt = 0; mt < 4; mt++)
        #pragma unroll
        for (int nt = 0; nt < 8; nt++)
            #pragma unroll
            for (int q = 0; q < 4; q++) acc[mt][nt][q] = 0.f;

    int st = 0;
    #pragma unroll 1
    for (int kc = 0; kc < NCH; kc++){
        if (kc + 1 < NCH) CP_WAIT1(); else CP_WAIT0();
        __syncthreads();
        if (kc + 2 < NCH){
            int st2 = st + 2; if (st2 >= 3) st2 -= 3;
            loadB(kc + 2, st2); CP_COMMIT();
        }

        uint32_t a[2][4][4];
        if (SKIP && kc == NCH - 1){
            #pragma unroll
            for (int mt = 0; mt < 4; mt++){
                int m = strip + mt*16 + r;
                int key = ((m & 15) >> 1) & 3;
                uint32_t base = sb + (uint32_t)(HALO + m*64);
                #pragma unroll
                for (int s = 0; s < 2; s++){
                    int slot = 2*s + kh;
                    ldmA(a[s][mt], base + (uint32_t)(((slot ^ key) << 4)));
                }
            }
        } else {
            const int tap = kc / NSUB;
            const int slotbase = (kc % NSUB) * 4;       // iho/8
            const int kz = tap/9, ky = (tap%9)/3, kx = tap%3;
            #pragma unroll
            for (int mt = 0; mt < 4; mt++){
                int hz = dzm[mt] + kz, hy = dym[mt] + ky, hx = dxm[mt] + kx;
                int hi = (hz*6 + hy)*18 + hx;
                int key = (INCH == 64) ? (hx & 7) : ((hx >> 1) & 3);
                uint32_t base = sb + (uint32_t)(hi*CHB);
                #pragma unroll
                for (int s = 0; s < 2; s++){
                    int slot = slotbase + 2*s + kh;
                    ldmA(a[s][mt], base + (uint32_t)((slot ^ key) << 4));
                }
            }
        }

        const unsigned char* B0 = smem + BOFF + st*4096;
        #pragma unroll
        for (int nt = 0; nt < 8; nt++){
            uint4 bv = *(const uint4*)(B0 + ((nt*32 + lane) << 4));
            #pragma unroll
            for (int mt = 0; mt < 4; mt++){
                mma16(acc[mt][nt], a[0][mt], bv.x, bv.y);
                mma16(acc[mt][nt], a[1][mt], bv.z, bv.w);
            }
        }
        st = (st == 2) ? 0 : st + 1;
    }

    // ---------------- epilogue ----------------
    #pragma unroll
    for (int mt = 0; mt < 4; mt++){
        #pragma unroll
        for (int half = 0; half < 2; half++){
            const int row = strip + mt*16 + g + 8*half;
            const int vz = z0 + (row >> 6);
            const int vy = y0 + ((row >> 4) & 3);
            const int vx = x0 + (row & 15);
            if (vz >= OUTD || vy >= OUTD || vx >= OUTD) continue;
            if constexpr (!SKIP){
                __half* dst = (__half*)outp + (((size_t)n*OUTD*OUTD*OUTD)
                            + (((size_t)vz*OUTD + vy)*OUTD + vx))*64;
                #pragma unroll
                for (int nt = 0; nt < 8; nt++){
                    const int c0 = nt*8 + 2*t;
                    float v0 = leaky(acc[mt][nt][2*half + 0] + sbias[c0]);
                    float v1 = leaky(acc[mt][nt][2*half + 1] + sbias[c0 + 1]);
                    *(__half2*)(dst + c0) = __floats2half2_rn(v0, v1);
                }
            } else {
                const size_t plane = (size_t)OUTD*OUTD*OUTD;
                float* base = (float*)outp + (size_t)n*64*plane
                            + (((size_t)vz*OUTD + vy)*OUTD + vx);
                #pragma unroll
                for (int nt = 0; nt < 8; nt++){
                    const int c0 = nt*8 + 2*t;
                    base[(size_t)c0*plane]       = leaky(acc[mt][nt][2*half + 0] + sbias[c0]);
                    base[(size_t)(c0 + 1)*plane] = leaky(acc[mt][nt][2*half + 1] + sbias[c0 + 1]);
                }
            }
        }
    }
}

// ---------------- launch ----------------
static const int SMEM_C1 = 648*64  + 3*4096 + 256;            // 54016
static const int SMEM_C2 = 648*128 + 16384 + 3*4096 + 256;    // 111872

extern "C" void kernel_launch(void* const* d_in, const int* in_sizes, int n_in,
                              void* d_out, int out_size)
{
    (void)in_sizes; (void)n_in; (void)out_size;
    const float* x       = (const float*)d_in[0];
    const float* s       = (const float*)d_in[1];
    const float* skip_w1 = (const float*)d_in[2];
    const float* skip_b1 = (const float*)d_in[3];
    const float* skip_w2 = (const float*)d_in[4];
    const float* skip_b2 = (const float*)d_in[5];
    const float* skip_w3 = (const float*)d_in[6];
    const float* skip_b3 = (const float*)d_in[7];
    const float* skip_wc = (const float*)d_in[8];
    const float* skip_bc = (const float*)d_in[9];
    const float* c1_w1   = (const float*)d_in[10];
    const float* c1_b1   = (const float*)d_in[11];
    const float* c1_w2   = (const float*)d_in[12];
    const float* c1_b2   = (const float*)d_in[13];
    const float* c1_w3   = (const float*)d_in[14];
    const float* c1_b3   = (const float*)d_in[15];
    const float* c1_wc   = (const float*)d_in[16];
    const float* c1_bc   = (const float*)d_in[17];
    const float* c2_w1   = (const float*)d_in[18];
    const float* c2_b1   = (const float*)d_in[19];
    const float* c2_w2   = (const float*)d_in[20];
    const float* c2_b2   = (const float*)d_in[21];
    const float* c2_w3   = (const float*)d_in[22];
    const float* c2_b3   = (const float*)d_in[23];
    const float* c2_wc   = (const float*)d_in[24];
    const float* c2_bc   = (const float*)d_in[25];

    __half *p_xcl, *p_h, *p_w1, *p_w2, *p_ws;
    cudaGetSymbolAddress((void**)&p_xcl, g_xcl);
    cudaGetSymbolAddress((void**)&p_h,   g_h);
    cudaGetSymbolAddress((void**)&p_w1,  g_wc1);
    cudaGetSymbolAddress((void**)&p_w2,  g_wc2);
    cudaGetSymbolAddress((void**)&p_ws,  g_wsk);

    cudaFuncSetAttribute((const void*)conv_mma<96,94,32,27,false>,
                         cudaFuncAttributeMaxDynamicSharedMemorySize, SMEM_C1);
    cudaFuncSetAttribute((const void*)conv_mma<94,92,64,55,true>,
                         cudaFuncAttributeMaxDynamicSharedMemorySize, SMEM_C2);

    prep_kernel<<<2, 256>>>(s, skip_w1, skip_b1, skip_w2, skip_b2, skip_w3, skip_b3,
                            skip_wc, p_ws, 64, 64, 32, 1);
    prep_kernel<<<2, 256>>>(s, c1_w1, c1_b1, c1_w2, c1_b2, c1_w3, c1_b3,
                            c1_wc, p_w1, 64, 64, 32, 27);
    prep_kernel<<<2, 256>>>(s, c2_w1, c2_b1, c2_w2, c2_b2, c2_w3, c2_b3,
                            c2_wc, p_w2, 128, 128, 64, 27);
    xconvert_kernel<<<dim3(96,96,2), 128>>>(x, p_xcl);

    // c1: xcl -> h (channels-last fp16, bias+leaky applied)
    conv_mma<96,94,32,27,false><<<dim3(6,24,48), 128, SMEM_C1>>>(
        p_xcl, p_w1, nullptr, nullptr, c1_bc, nullptr, (void*)p_h);

    // c2 + fused skip + both biases + final leaky -> NCDHW fp32 out
    conv_mma<94,92,64,55,true><<<dim3(6,23,46), 128, SMEM_C2>>>(
        p_h, p_w2, p_ws, p_xcl, c2_bc, skip_bc, d_out);
}